// round 12
// baseline (speedup 1.0000x reference)
#include <cuda_runtime.h>
#include <cuda_bf16.h>
#include <cstdint>

#define RM 8192
#define RN 8192
#define DB 256
#define TM 128
#define TN 256
#define TILES_N 32
#define STAGE_A (TM*DB)               // 32 KB
#define STAGE_B (TN*DB)               // 64 KB
#define STAGE_BYTES (STAGE_A+STAGE_B) // 96 KB
#define SMEM0 1024
#define IDXB 17408                    // uint16 idx table, padded to 1024
#define SMEM_STAGE (SMEM0 + IDXB)     // 18432, 1024-aligned
#define SMEM_TOTAL (SMEM_STAGE + 2*STAGE_BYTES)   // 211968
#define MAIN_GRID 148
#define NTHREADS 256
#define QSCALE 20.0f
#define INV_SCALE (1.0f/(QSCALE*QSCALE))
#define S2I 400
#define S2I2 800

// g_Afull has TM extra rows; statically zero-initialized and NEVER written,
// so pad rows stay zero across graph replays.
__device__ __align__(1024) signed char g_Afull[(RM+TM)*DB];
__device__ __align__(1024) signed char g_B[RN*DB];
__device__ int g_flag[RM];
__device__ double g_acc;
__device__ unsigned g_done;

__device__ __forceinline__ uint32_t smem_u32(const void* p){
    uint32_t a; asm("{ .reg .u64 t; cvta.to.shared.u64 t, %1; cvt.u32.u64 %0, t; }":"=r"(a):"l"(p)); return a;
}
#define SWX(r,c) (((c)&0x80) | (((c)&0x7F) ^ (((r)&7)<<4)))
#define CPA16(d,s) asm volatile("cp.async.cg.shared.global [%0], [%1], 16;"::"r"(d),"l"(s):"memory")
#define CP_COMMIT() asm volatile("cp.async.commit_group;":::"memory")
#define CP_WAIT1()  asm volatile("cp.async.wait_group 1;":::"memory")

#define LDSM4(r0,r1,r2,r3,addr) \
    asm volatile("ldmatrix.sync.aligned.m8n8.x4.shared.b16 {%0,%1,%2,%3}, [%4];" \
        : "=r"(r0),"=r"(r1),"=r"(r2),"=r"(r3) : "r"(addr))
#define MMAS8(c,a,b0,b1) \
    asm volatile("mma.sync.aligned.m16n8k32.row.col.s32.s8.s8.s32 " \
        "{%0,%1,%2,%3},{%4,%5,%6,%7},{%8,%9},{%0,%1,%2,%3};" \
        : "+r"((c)[0]),"+r"((c)[1]),"+r"((c)[2]),"+r"((c)[3]) \
        : "r"((a)[0]),"r"((a)[1]),"r"((a)[2]),"r"((a)[3]),"r"(b0),"r"(b1))

// A rows gathered via smem idx table; B rows direct.
__device__ __forceinline__ void load_tile(int tm, int tn, int stg, int tid, uint32_t sb,
                                          const uint16_t* __restrict__ idxs){
    uint32_t st  = sb + SMEM_STAGE + stg*STAGE_BYTES;
    uint32_t stB = st + STAGE_A;
    const uint16_t* idx = idxs + tm*TM;
    const signed char* Bg = g_B + (size_t)(tn*TN)*DB;
    #pragma unroll
    for(int j=0;j<8;j++){
        int u = tid + j*NTHREADS;
        int r = u>>4, cc = (u&15)*16;
        int orig = idx[r];
        CPA16(st + r*256 + SWX(r,cc), g_Afull + (size_t)orig*DB + cc);
    }
    #pragma unroll
    for(int j=0;j<16;j++){
        int u = tid + j*NTHREADS;
        int r = u>>4, cc = (u&15)*16;
        CPA16(stB + r*256 + SWX(r,cc), Bg + (size_t)r*DB + cc);
    }
}

__global__ void __launch_bounds__(NTHREADS,1) frag_main(float* out){
    extern __shared__ char smem[];
    uint32_t sb = smem_u32(smem);
    uint16_t* idxs = (uint16_t*)(smem + SMEM0);
    int tid = threadIdx.x, wid = tid>>5, lane = tid&31;
    int bid = blockIdx.x, grid = gridDim.x;

    // ---- prologue: per-CTA redundant scan of flags -> smem idx table ----
    __shared__ int ws[8];
    __shared__ int sh_tot;
    {
        int f[32], sc = 0;
        int t32 = tid*32;
        #pragma unroll
        for(int i=0;i<32;i++){ f[i] = g_flag[t32+i]; sc += f[i]; }
        int pre = sc;
        #pragma unroll
        for(int o=1;o<32;o<<=1){ int v = __shfl_up_sync(0xffffffffu, pre, o); if(lane>=o) pre += v; }
        if(lane==31) ws[wid] = pre;
        __syncthreads();
        if(wid==0 && lane<8){
            int v = ws[lane];
            #pragma unroll
            for(int o=1;o<8;o<<=1){ int x = __shfl_up_sync(0xffu, v, o); if(lane>=o) v += x; }
            ws[lane] = v;
        }
        __syncthreads();
        int p = (wid>0 ? ws[wid-1] : 0) + pre - sc;
        #pragma unroll
        for(int i=0;i<32;i++){
            if(f[i]){ idxs[p] = (uint16_t)(t32 + i); p++; }
        }
        if(tid==NTHREADS-1) sh_tot = p;
        __syncthreads();
    }
    int count = sh_tot;
    int ntm = (count + TM - 1)/TM;
    int pad_end = ntm*TM;
    for(int r = count + tid; r < pad_end; r += NTHREADS)
        idxs[r] = (uint16_t)(RM + (r - count));   // zero pad rows of g_Afull
    __syncthreads();

    // ---- GEMM + fused loss ----
    int m0 = (wid & 1)*64, n0 = (wid >> 1)*64;
    uint32_t untm = (uint32_t)ntm;
    uint32_t unt  = untm * TILES_N;

    uint32_t perm = (lane&7)<<4;
    uint32_t halfoff = (lane>>4)*16;
    uint32_t rowA[4], rowB[4];
    #pragma unroll
    for(int f=0;f<4;f++){
        rowA[f] = (m0 + f*16 + (lane&15))*256;
        rowB[f] = (n0 + f*16 + (lane&15))*256;
    }

    int c[4][8][4];
    #pragma unroll
    for(int i=0;i<4;i++)
        #pragma unroll
        for(int j=0;j<8;j++)
            #pragma unroll
            for(int k=0;k<4;k++) c[i][j][k] = S2I;

    float acc = 0.f;

    if((uint32_t)bid < unt){
        uint32_t tn0 = (uint32_t)bid / untm, tm0 = (uint32_t)bid - tn0*untm;
        load_tile(tm0, tn0, 0, tid, sb, idxs);
    }
    CP_COMMIT();

    int lt = 0;
    for(uint32_t t=bid; t<unt; t+=grid, lt++){
        uint32_t tn = t / untm, tm = t - tn*untm;
        int stg = lt & 1;

        __syncthreads();
        uint32_t t2 = t + grid;
        if(t2 < unt){
            uint32_t tn2 = t2 / untm, tm2 = t2 - tn2*untm;
            load_tile(tm2, tn2, stg^1, tid, sb, idxs);
        }
        CP_COMMIT();
        CP_WAIT1();
        __syncthreads();

        int rb0[4], rb1[4];
        #pragma unroll
        for(int mf=0;mf<4;mf++){
            int growf = tm*TM + m0 + mf*16;
            int v0 = idxs[growf + (lane>>2)];
            int v1 = idxs[growf + (lane>>2) + 8];
            rb0[mf] = (v0 < RM) ? (v0 >> 5) : -1;
            rb1[mf] = (v1 < RM) ? (v1 >> 5) : -1;
        }

        uint32_t stA = sb + SMEM_STAGE + stg*STAGE_BYTES;
        uint32_t stB = stA + STAGE_A;
        #pragma unroll
        for(int ks=0;ks<8;ks++){
            uint32_t kb = ks*32 + halfoff;
            uint32_t kx = (kb & 0x80) | ((kb & 0x7F) ^ perm);
            uint32_t a[4][4], b[4][4];
            #pragma unroll
            for(int f=0;f<4;f++) LDSM4(a[f][0],a[f][1],a[f][2],a[f][3], stA + rowA[f] + kx);
            #pragma unroll
            for(int f=0;f<4;f++) LDSM4(b[f][0],b[f][1],b[f][2],b[f][3], stB + rowB[f] + kx);
            #pragma unroll
            for(int mf=0;mf<4;mf++)
                #pragma unroll
                for(int nb=0;nb<4;nb++){
                    MMAS8(c[mf][2*nb],   a[mf], b[nb][0], b[nb][2]);
                    MMAS8(c[mf][2*nb+1], a[mf], b[nb][1], b[nb][3]);
                }
        }

        int cb_lo = tn*8 + (n0>>5);
        int cb_hi = cb_lo + 1;
        #pragma unroll
        for(int mf=0;mf<4;mf++){
            int r0 = 0, r1 = 0;
            bool slow = __any_sync(0xffffffffu,
                 rb0[mf]==cb_lo || rb0[mf]==cb_hi || rb1[mf]==cb_lo || rb1[mf]==cb_hi);
            if(!slow){
                #pragma unroll
                for(int j=0;j<8;j++){
                    int* cc = c[mf][j];
                    r0 += max(cc[0],0) + max(cc[1],0);
                    r1 += max(cc[2],0) + max(cc[3],0);
                    cc[0]=S2I; cc[1]=S2I; cc[2]=S2I; cc[3]=S2I;
                }
            } else {
                #pragma unroll
                for(int nb=0;nb<4;nb++){
                    #pragma unroll
                    for(int sub=0;sub<2;sub++){
                        int cb = cb_lo + (nb>>1);
                        int* cc = c[mf][2*nb+sub];
                        bool p0 = (rb0[mf]==cb), p1 = (rb1[mf]==cb);
                        r0 += p0 ? (max(S2I2-cc[0],0)+max(S2I2-cc[1],0))
                                 : (max(cc[0],0)+max(cc[1],0));
                        r1 += p1 ? (max(S2I2-cc[2],0)+max(S2I2-cc[3],0))
                                 : (max(cc[2],0)+max(cc[3],0));
                        cc[0]=S2I; cc[1]=S2I; cc[2]=S2I; cc[3]=S2I;
                    }
                }
            }
            acc += (rb0[mf]>=0 ? (float)r0 : 0.f) + (rb1[mf]>=0 ? (float)r1 : 0.f);
        }
    }

    #pragma unroll
    for(int o=16;o;o>>=1) acc += __shfl_xor_sync(0xffffffffu, acc, o);
    __shared__ float red[8];
    if(lane==0) red[wid] = acc;
    __syncthreads();
    if(tid==0){
        double s = 0.0;
        #pragma unroll
        for(int w=0;w<8;w++) s += (double)red[w];
        s *= (double)INV_SCALE;
        atomicAdd(&g_acc, s);
        __threadfence();
        unsigned prev = atomicAdd(&g_done, 1u);
        if(prev == gridDim.x - 1){
            __threadfence();
            double tot = *((volatile double*)&g_acc);
            out[0] = (float)(tot / 256.0);
        }
    }
}

// prep (R10-proven): quantize face->g_Afull (+flags), ner->g_B; clear accumulators
__global__ void frag_prep(const float* __restrict__ face, const float* __restrict__ ner){
    int tid = threadIdx.x, wid = tid>>5, lane = tid&31;
    if(blockIdx.x==0 && tid==0){ g_acc = 0.0; g_done = 0u; }
    int row = blockIdx.x*8 + wid;
    bool isface = row < RM;
    const float* src = isface ? (face + (size_t)row*256) : (ner + (size_t)(row-RM)*256);
    signed char* dst = isface ? (g_Afull + (size_t)row*DB) : (g_B + (size_t)(row-RM)*DB);

    float4 v0 = ((const float4*)src)[lane];
    float4 v1 = ((const float4*)src)[lane+32];
    char4 q0, q1;
    #define QZ(x) (signed char)max(-127, min(127, __float2int_rn((x)*QSCALE)))
    q0.x=QZ(v0.x); q0.y=QZ(v0.y); q0.z=QZ(v0.z); q0.w=QZ(v0.w);
    q1.x=QZ(v1.x); q1.y=QZ(v1.y); q1.z=QZ(v1.z); q1.w=QZ(v1.w);
    #undef QZ
    ((char4*)dst)[lane]    = q0;
    ((char4*)dst)[lane+32] = q1;

    if(isface){
        float s = v0.x+v0.y+v0.z+v0.w + v1.x+v1.y+v1.z+v1.w;
        #pragma unroll
        for(int o=16;o;o>>=1) s += __shfl_xor_sync(0xffffffffu, s, o);
        if(lane==0) g_flag[row] = (s != 0.f) ? 1 : 0;
    }
}

extern "C" void kernel_launch(void* const* d_in, const int* in_sizes, int n_in,
                              void* d_out, int out_size){
    const float* face = (const float*)d_in[0];
    const float* ner  = (const float*)d_in[1];
    float* out = (float*)d_out;

    cudaFuncSetAttribute(frag_main, cudaFuncAttributeMaxDynamicSharedMemorySize, SMEM_TOTAL);

    frag_prep<<<(RM+RN)/8, 256>>>(face, ner);
    frag_main<<<MAIN_GRID, NTHREADS, SMEM_TOTAL>>>(out);
}

// round 14
// speedup vs baseline: 1.0968x; 1.0968x over previous
#include <cuda_runtime.h>
#include <cuda_bf16.h>
#include <cstdint>

#define RM 8192
#define RN 8192
#define DB 256
#define TM 128
#define TN 256
#define TILES_N 32
#define STAGE_A (TM*DB)               // 32 KB
#define STAGE_B (TN*DB)               // 64 KB
#define STAGE_BYTES (STAGE_A+STAGE_B) // 96 KB
#define SMEM0 1024
#define SMEM_TOTAL (SMEM0 + 2*STAGE_BYTES)
#define MAIN_GRID 148
#define NTHREADS 256
#define QSCALE 20.0f
#define INV_SCALE (1.0f/(QSCALE*QSCALE))
#define S2I 400
#define S2I2 800

// g_Afull has TM extra rows; statically zero-initialized and NEVER written,
// so pad rows stay zero across graph replays.
__device__ __align__(1024) signed char g_Afull[(RM+TM)*DB];
__device__ __align__(1024) signed char g_B[RN*DB];
__device__ int g_flag[RM];
__device__ int g_idx[RM+TM];    // compacted row -> original row (pads -> >=RM)
__device__ int g_rb[RM+TM];     // compacted row -> batch idx (-1 = pad)
__device__ int g_ntm;
__device__ double g_acc;
__device__ unsigned g_done;

__device__ __forceinline__ uint32_t smem_u32(const void* p){
    uint32_t a; asm("{ .reg .u64 t; cvta.to.shared.u64 t, %1; cvt.u32.u64 %0, t; }":"=r"(a):"l"(p)); return a;
}
#define SWX(r,c) (((c)&0x80) | (((c)&0x7F) ^ (((r)&7)<<4)))
#define CPA16(d,s) asm volatile("cp.async.cg.shared.global [%0], [%1], 16;"::"r"(d),"l"(s):"memory")
#define CP_COMMIT() asm volatile("cp.async.commit_group;":::"memory")
#define CP_WAIT1()  asm volatile("cp.async.wait_group 1;":::"memory")

#define LDSM4(r0,r1,r2,r3,addr) \
    asm volatile("ldmatrix.sync.aligned.m8n8.x4.shared.b16 {%0,%1,%2,%3}, [%4];" \
        : "=r"(r0),"=r"(r1),"=r"(r2),"=r"(r3) : "r"(addr))
#define MMAS8(c,a,b0,b1) \
    asm volatile("mma.sync.aligned.m16n8k32.row.col.s32.s8.s8.s32 " \
        "{%0,%1,%2,%3},{%4,%5,%6,%7},{%8,%9},{%0,%1,%2,%3};" \
        : "+r"((c)[0]),"+r"((c)[1]),"+r"((c)[2]),"+r"((c)[3]) \
        : "r"((a)[0]),"r"((a)[1]),"r"((a)[2]),"r"((a)[3]),"r"(b0),"r"(b1))

// A rows gathered via g_idx; B rows direct.
__device__ __forceinline__ void load_tile(int tm, int tn, int stg, int tid, uint32_t sb){
    uint32_t st  = sb + SMEM0 + stg*STAGE_BYTES;
    uint32_t stB = st + STAGE_A;
    const int* idx = g_idx + tm*TM;
    const signed char* Bg = g_B + (size_t)(tn*TN)*DB;
    #pragma unroll
    for(int j=0;j<8;j++){
        int u = tid + j*NTHREADS;
        int r = u>>4, cc = (u&15)*16;
        int orig = __ldg(&idx[r]);
        CPA16(st + r*256 + SWX(r,cc), g_Afull + (size_t)orig*DB + cc);
    }
    #pragma unroll
    for(int j=0;j<16;j++){
        int u = tid + j*NTHREADS;
        int r = u>>4, cc = (u&15)*16;
        CPA16(stB + r*256 + SWX(r,cc), Bg + (size_t)r*DB + cc);
    }
}

__global__ void __launch_bounds__(NTHREADS,1) frag_main(float* out){
    extern __shared__ char smem[];
    uint32_t sb = smem_u32(smem);
    int tid = threadIdx.x, wid = tid>>5, lane = tid&31;
    int bid = blockIdx.x, grid = gridDim.x;

    int m0 = (wid & 1)*64, n0 = (wid >> 1)*64;
    uint32_t untm = (uint32_t)g_ntm;
    uint32_t unt  = untm * TILES_N;

    uint32_t perm = (lane&7)<<4;
    uint32_t halfoff = (lane>>4)*16;
    uint32_t rowA[4], rowB[4];
    #pragma unroll
    for(int f=0;f<4;f++){
        rowA[f] = (m0 + f*16 + (lane&15))*256;
        rowB[f] = (n0 + f*16 + (lane&15))*256;
    }

    int c[4][8][4];
    #pragma unroll
    for(int i=0;i<4;i++)
        #pragma unroll
        for(int j=0;j<8;j++)
            #pragma unroll
            for(int k=0;k<4;k++) c[i][j][k] = S2I;

    float acc = 0.f;

    if((uint32_t)bid < unt){
        uint32_t tn0 = (uint32_t)bid / untm, tm0 = (uint32_t)bid - tn0*untm;
        load_tile(tm0, tn0, 0, tid, sb);
    }
    CP_COMMIT();

    int lt = 0;
    for(uint32_t t=bid; t<unt; t+=grid, lt++){
        uint32_t tn = t / untm, tm = t - tn*untm;
        int stg = lt & 1;

        __syncthreads();
        uint32_t t2 = t + grid;
        if(t2 < unt){
            uint32_t tn2 = t2 / untm, tm2 = t2 - tn2*untm;
            load_tile(tm2, tn2, stg^1, tid, sb);
        }
        CP_COMMIT();
        CP_WAIT1();
        __syncthreads();

        int rb0[4], rb1[4];
        #pragma unroll
        for(int mf=0;mf<4;mf++){
            int growf = tm*TM + m0 + mf*16;
            rb0[mf] = g_rb[growf + (lane>>2)];
            rb1[mf] = g_rb[growf + (lane>>2) + 8];
        }

        uint32_t stA = sb + SMEM0 + stg*STAGE_BYTES;
        uint32_t stB = stA + STAGE_A;
        #pragma unroll
        for(int ks=0;ks<8;ks++){
            uint32_t kb = ks*32 + halfoff;
            uint32_t kx = (kb & 0x80) | ((kb & 0x7F) ^ perm);
            uint32_t a[4][4], b[4][4];
            #pragma unroll
            for(int f=0;f<4;f++) LDSM4(a[f][0],a[f][1],a[f][2],a[f][3], stA + rowA[f] + kx);
            #pragma unroll
            for(int f=0;f<4;f++) LDSM4(b[f][0],b[f][1],b[f][2],b[f][3], stB + rowB[f] + kx);
            #pragma unroll
            for(int mf=0;mf<4;mf++)
                #pragma unroll
                for(int nb=0;nb<4;nb++){
                    MMAS8(c[mf][2*nb],   a[mf], b[nb][0], b[nb][2]);
                    MMAS8(c[mf][2*nb+1], a[mf], b[nb][1], b[nb][3]);
                }
        }

        int cb_lo = tn*8 + (n0>>5);
        int cb_hi = cb_lo + 1;
        #pragma unroll
        for(int mf=0;mf<4;mf++){
            int r0 = 0, r1 = 0;
            bool slow = __any_sync(0xffffffffu,
                 rb0[mf]==cb_lo || rb0[mf]==cb_hi || rb1[mf]==cb_lo || rb1[mf]==cb_hi);
            if(!slow){
                #pragma unroll
                for(int j=0;j<8;j++){
                    int* cc = c[mf][j];
                    r0 += max(cc[0],0) + max(cc[1],0);
                    r1 += max(cc[2],0) + max(cc[3],0);
                    cc[0]=S2I; cc[1]=S2I; cc[2]=S2I; cc[3]=S2I;
                }
            } else {
                #pragma unroll
                for(int nb=0;nb<4;nb++){
                    #pragma unroll
                    for(int sub=0;sub<2;sub++){
                        int cb = cb_lo + (nb>>1);
                        int* cc = c[mf][2*nb+sub];
                        bool p0 = (rb0[mf]==cb), p1 = (rb1[mf]==cb);
                        r0 += p0 ? (max(S2I2-cc[0],0)+max(S2I2-cc[1],0))
                                 : (max(cc[0],0)+max(cc[1],0));
                        r1 += p1 ? (max(S2I2-cc[2],0)+max(S2I2-cc[3],0))
                                 : (max(cc[2],0)+max(cc[3],0));
                        cc[0]=S2I; cc[1]=S2I; cc[2]=S2I; cc[3]=S2I;
                    }
                }
            }
            acc += (rb0[mf]>=0 ? (float)r0 : 0.f) + (rb1[mf]>=0 ? (float)r1 : 0.f);
        }
    }

    #pragma unroll
    for(int o=16;o;o>>=1) acc += __shfl_xor_sync(0xffffffffu, acc, o);
    __shared__ float red[8];
    if(lane==0) red[wid] = acc;
    __syncthreads();
    if(tid==0){
        double s = 0.0;
        #pragma unroll
        for(int w=0;w<8;w++) s += (double)red[w];
        s *= (double)INV_SCALE;
        atomicAdd(&g_acc, s);
        __threadfence();
        unsigned prev = atomicAdd(&g_done, 1u);
        if(prev == gridDim.x - 1){
            __threadfence();
            double tot = *((volatile double*)&g_acc);
            out[0] = (float)(tot / 256.0);
        }
    }
}

// prep: each warp quantizes 1 face row + 1 ner row (4 LDG.128 in flight)
__global__ void __launch_bounds__(NTHREADS,2)
frag_prep(const float* __restrict__ face, const float* __restrict__ ner){
    int tid = threadIdx.x, wid = tid>>5, lane = tid&31;
    if(blockIdx.x==0 && tid==0){ g_acc = 0.0; g_done = 0u; }
    int row = blockIdx.x*8 + wid;                 // grid = RM/8 = 1024
    const float* fs = face + (size_t)row*256;
    const float* ns = ner  + (size_t)row*256;

    float4 f0 = ((const float4*)fs)[lane];
    float4 f1 = ((const float4*)fs)[lane+32];
    float4 e0 = ((const float4*)ns)[lane];
    float4 e1 = ((const float4*)ns)[lane+32];

    #define QZ(x) (signed char)max(-127, min(127, __float2int_rn((x)*QSCALE)))
    char4 qa0 = { QZ(f0.x),QZ(f0.y),QZ(f0.z),QZ(f0.w) };
    char4 qa1 = { QZ(f1.x),QZ(f1.y),QZ(f1.z),QZ(f1.w) };
    char4 qb0 = { QZ(e0.x),QZ(e0.y),QZ(e0.z),QZ(e0.w) };
    char4 qb1 = { QZ(e1.x),QZ(e1.y),QZ(e1.z),QZ(e1.w) };
    #undef QZ
    ((char4*)(g_Afull + (size_t)row*DB))[lane]    = qa0;
    ((char4*)(g_Afull + (size_t)row*DB))[lane+32] = qa1;
    ((char4*)(g_B     + (size_t)row*DB))[lane]    = qb0;
    ((char4*)(g_B     + (size_t)row*DB))[lane+32] = qb1;

    float s = f0.x+f0.y+f0.z+f0.w + f1.x+f1.y+f1.z+f1.w;
    #pragma unroll
    for(int o=16;o;o>>=1) s += __shfl_xor_sync(0xffffffffu, s, o);
    if(lane==0) g_flag[row] = (s != 0.f) ? 1 : 0;
}

// scan: single block; flags -> g_idx/g_rb (+pads), g_ntm
__global__ void __launch_bounds__(1024,1) frag_scan(){
    __shared__ int ws[32];
    __shared__ int tot;
    int t = threadIdx.x, lane = t&31, w = t>>5;
    int f[8], s = 0;
    #pragma unroll
    for(int i=0;i<8;i++){ f[i] = g_flag[t*8+i]; s += f[i]; }
    int pre = s;
    #pragma unroll
    for(int o=1;o<32;o<<=1){ int v = __shfl_up_sync(0xffffffffu, pre, o); if(lane>=o) pre += v; }
    if(lane==31) ws[w] = pre;
    __syncthreads();
    if(w==0){
        int v = ws[lane];
        #pragma unroll
        for(int o=1;o<32;o<<=1){ int x = __shfl_up_sync(0xffffffffu, v, o); if(lane>=o) v += x; }
        ws[lane] = v;
    }
    __syncthreads();
    int base = (w>0 ? ws[w-1] : 0) + pre - s;
    int p = base;
    #pragma unroll
    for(int i=0;i<8;i++){
        int row = t*8+i;
        if(f[i]){ g_idx[p] = row; g_rb[p] = row >> 5; p++; }
    }
    if(t==1023){ tot = p; g_ntm = (p + TM - 1)/TM; }
    __syncthreads();
    int count = tot, pad_end = ((count + TM - 1)/TM)*TM;
    for(int r = count + t; r < pad_end; r += 1024){
        g_idx[r] = RM + (r - count);   // zero pad rows of g_Afull (never written)
        g_rb[r]  = -1;
    }
}

extern "C" void kernel_launch(void* const* d_in, const int* in_sizes, int n_in,
                              void* d_out, int out_size){
    const float* face = (const float*)d_in[0];
    const float* ner  = (const float*)d_in[1];
    float* out = (float*)d_out;

    cudaFuncSetAttribute(frag_main, cudaFuncAttributeMaxDynamicSharedMemorySize, SMEM_TOTAL);

    frag_prep<<<RM/8, NTHREADS>>>(face, ner);
    frag_scan<<<1, 1024>>>();
    frag_main<<<MAIN_GRID, NTHREADS, SMEM_TOTAL>>>(out);
}

// round 15
// speedup vs baseline: 1.1216x; 1.0227x over previous
#include <cuda_runtime.h>
#include <cuda_bf16.h>
#include <cstdint>

#define RM 8192
#define RN 8192
#define DB 256
#define TM 128
#define TN 256
#define TILES_N 32
#define STAGE_A (TM*DB)               // 32 KB
#define STAGE_B (TN*DB)               // 64 KB
#define STAGE_BYTES (STAGE_A+STAGE_B) // 96 KB
#define SMEM0 1024
#define SMEM_TOTAL (SMEM0 + 2*STAGE_BYTES)
#define MAIN_GRID 148
#define NTHREADS 256
#define QSCALE 20.0f
#define INV_SCALE (1.0f/(QSCALE*QSCALE))
#define S2I 400
#define S2I2 800

// g_Afull has TM extra rows; statically zero-initialized and NEVER written,
// so pad rows stay zero across graph replays.
__device__ __align__(1024) signed char g_Afull[(RM+TM)*DB];
__device__ __align__(1024) signed char g_B[RN*DB];
__device__ int g_flag[RM];
__device__ int g_idx[RM+TM];
__device__ int g_rb[RM+TM];
__device__ int g_ntm;
__device__ double g_acc;
__device__ unsigned g_done;

__device__ __forceinline__ uint32_t smem_u32(const void* p){
    uint32_t a; asm("{ .reg .u64 t; cvta.to.shared.u64 t, %1; cvt.u32.u64 %0, t; }":"=r"(a):"l"(p)); return a;
}
#define SWX(r,c) (((c)&0x80) | (((c)&0x7F) ^ (((r)&7)<<4)))
#define CPA16(d,s) asm volatile("cp.async.cg.shared.global [%0], [%1], 16;"::"r"(d),"l"(s):"memory")
#define CP_COMMIT() asm volatile("cp.async.commit_group;":::"memory")
#define CP_WAIT1()  asm volatile("cp.async.wait_group 1;":::"memory")

#define LDSM4(r0,r1,r2,r3,addr) \
    asm volatile("ldmatrix.sync.aligned.m8n8.x4.shared.b16 {%0,%1,%2,%3}, [%4];" \
        : "=r"(r0),"=r"(r1),"=r"(r2),"=r"(r3) : "r"(addr))
#define MMAS8(c,a,b0,b1) \
    asm volatile("mma.sync.aligned.m16n8k32.row.col.s32.s8.s8.s32 " \
        "{%0,%1,%2,%3},{%4,%5,%6,%7},{%8,%9},{%0,%1,%2,%3};" \
        : "+r"((c)[0]),"+r"((c)[1]),"+r"((c)[2]),"+r"((c)[3]) \
        : "r"((a)[0]),"r"((a)[1]),"r"((a)[2]),"r"((a)[3]),"r"(b0),"r"(b1))

// A rows gathered via g_idx; B rows direct.
__device__ __forceinline__ void load_tile(int tm, int tn, int stg, int tid, uint32_t sb){
    uint32_t st  = sb + SMEM0 + stg*STAGE_BYTES;
    uint32_t stB = st + STAGE_A;
    const int* idx = g_idx + tm*TM;
    const signed char* Bg = g_B + (size_t)(tn*TN)*DB;
    #pragma unroll
    for(int j=0;j<8;j++){
        int u = tid + j*NTHREADS;
        int r = u>>4, cc = (u&15)*16;
        int orig = __ldg(&idx[r]);
        CPA16(st + r*256 + SWX(r,cc), g_Afull + (size_t)orig*DB + cc);
    }
    #pragma unroll
    for(int j=0;j<16;j++){
        int u = tid + j*NTHREADS;
        int r = u>>4, cc = (u&15)*16;
        CPA16(stB + r*256 + SWX(r,cc), Bg + (size_t)r*DB + cc);
    }
}

__global__ void __launch_bounds__(NTHREADS,1) frag_main(float* out){
    extern __shared__ char smem[];
    uint32_t sb = smem_u32(smem);
    int tid = threadIdx.x, wid = tid>>5, lane = tid&31;
    int bid = blockIdx.x, grid = gridDim.x;

    int m0 = (wid & 1)*64, n0 = (wid >> 1)*64;
    uint32_t untm = (uint32_t)g_ntm;
    uint32_t unt  = untm * TILES_N;

    uint32_t perm = (lane&7)<<4;
    uint32_t halfoff = (lane>>4)*16;
    uint32_t rowA[4], rowB[4];
    #pragma unroll
    for(int f=0;f<4;f++){
        rowA[f] = (m0 + f*16 + (lane&15))*256;
        rowB[f] = (n0 + f*16 + (lane&15))*256;
    }

    int c[4][8][4];
    #pragma unroll
    for(int i=0;i<4;i++)
        #pragma unroll
        for(int j=0;j<8;j++)
            #pragma unroll
            for(int k=0;k<4;k++) c[i][j][k] = S2I;

    float acc = 0.f;

    if((uint32_t)bid < unt){
        uint32_t tn0 = (uint32_t)bid / untm, tm0 = (uint32_t)bid - tn0*untm;
        load_tile(tm0, tn0, 0, tid, sb);
    }
    CP_COMMIT();

    int lt = 0;
    for(uint32_t t=bid; t<unt; t+=grid, lt++){
        uint32_t tn = t / untm, tm = t - tn*untm;
        int stg = lt & 1;

        __syncthreads();
        uint32_t t2 = t + grid;
        if(t2 < unt){
            uint32_t tn2 = t2 / untm, tm2 = t2 - tn2*untm;
            load_tile(tm2, tn2, stg^1, tid, sb);
        }
        CP_COMMIT();
        CP_WAIT1();
        __syncthreads();

        int rb0[4], rb1[4];
        #pragma unroll
        for(int mf=0;mf<4;mf++){
            int growf = tm*TM + m0 + mf*16;
            rb0[mf] = g_rb[growf + (lane>>2)];
            rb1[mf] = g_rb[growf + (lane>>2) + 8];
        }

        uint32_t stA = sb + SMEM0 + stg*STAGE_BYTES;
        uint32_t stB = stA + STAGE_A;

        // fragment double-buffer: prefetch ks+1 LDSMs before ks MMAs
        uint32_t a[2][4][4], b[2][4][4];
        #define LOAD_FRAGS(buf, ksv) do{ \
            uint32_t kb = (uint32_t)(ksv)*32 + halfoff; \
            uint32_t kx = (kb & 0x80) | ((kb & 0x7F) ^ perm); \
            _Pragma("unroll") \
            for(int f=0;f<4;f++) LDSM4(a[buf][f][0],a[buf][f][1],a[buf][f][2],a[buf][f][3], stA + rowA[f] + kx); \
            _Pragma("unroll") \
            for(int f=0;f<4;f++) LDSM4(b[buf][f][0],b[buf][f][1],b[buf][f][2],b[buf][f][3], stB + rowB[f] + kx); \
        }while(0)

        LOAD_FRAGS(0, 0);
        #pragma unroll
        for(int ks=0;ks<8;ks++){
            int cur = ks&1;
            if(ks<7) LOAD_FRAGS(cur^1, ks+1);
            #pragma unroll
            for(int mf=0;mf<4;mf++)
                #pragma unroll
                for(int nb=0;nb<4;nb++){
                    MMAS8(c[mf][2*nb],   a[cur][mf], b[cur][nb][0], b[cur][nb][2]);
                    MMAS8(c[mf][2*nb+1], a[cur][mf], b[cur][nb][1], b[cur][nb][3]);
                }
        }
        #undef LOAD_FRAGS

        int cb_lo = tn*8 + (n0>>5);
        int cb_hi = cb_lo + 1;
        #pragma unroll
        for(int mf=0;mf<4;mf++){
            int r0 = 0, r1 = 0;
            bool slow = __any_sync(0xffffffffu,
                 rb0[mf]==cb_lo || rb0[mf]==cb_hi || rb1[mf]==cb_lo || rb1[mf]==cb_hi);
            if(!slow){
                #pragma unroll
                for(int j=0;j<8;j++){
                    int* cc = c[mf][j];
                    r0 += max(cc[0],0) + max(cc[1],0);
                    r1 += max(cc[2],0) + max(cc[3],0);
                    cc[0]=S2I; cc[1]=S2I; cc[2]=S2I; cc[3]=S2I;
                }
            } else {
                #pragma unroll
                for(int nb=0;nb<4;nb++){
                    #pragma unroll
                    for(int sub=0;sub<2;sub++){
                        int cb = cb_lo + (nb>>1);
                        int* cc = c[mf][2*nb+sub];
                        bool p0 = (rb0[mf]==cb), p1 = (rb1[mf]==cb);
                        r0 += p0 ? (max(S2I2-cc[0],0)+max(S2I2-cc[1],0))
                                 : (max(cc[0],0)+max(cc[1],0));
                        r1 += p1 ? (max(S2I2-cc[2],0)+max(S2I2-cc[3],0))
                                 : (max(cc[2],0)+max(cc[3],0));
                        cc[0]=S2I; cc[1]=S2I; cc[2]=S2I; cc[3]=S2I;
                    }
                }
            }
            acc += (rb0[mf]>=0 ? (float)r0 : 0.f) + (rb1[mf]>=0 ? (float)r1 : 0.f);
        }
    }

    #pragma unroll
    for(int o=16;o;o>>=1) acc += __shfl_xor_sync(0xffffffffu, acc, o);
    __shared__ float red[8];
    if(lane==0) red[wid] = acc;
    __syncthreads();
    if(tid==0){
        double s = 0.0;
        #pragma unroll
        for(int w=0;w<8;w++) s += (double)red[w];
        s *= (double)INV_SCALE;
        atomicAdd(&g_acc, s);
        __threadfence();
        unsigned prev = atomicAdd(&g_done, 1u);
        if(prev == gridDim.x - 1){
            __threadfence();
            double tot = *((volatile double*)&g_acc);
            out[0] = (float)(tot / 256.0);
        }
    }
}

// prep (R10 exact): quantize face->g_Afull (+flags), ner->g_B; clear accumulators
__global__ void frag_prep(const float* __restrict__ face, const float* __restrict__ ner){
    int tid = threadIdx.x, wid = tid>>5, lane = tid&31;
    if(blockIdx.x==0 && tid==0){ g_acc = 0.0; g_done = 0u; }
    int row = blockIdx.x*8 + wid;
    bool isface = row < RM;
    const float* src = isface ? (face + (size_t)row*256) : (ner + (size_t)(row-RM)*256);
    signed char* dst = isface ? (g_Afull + (size_t)row*DB) : (g_B + (size_t)(row-RM)*DB);

    float4 v0 = ((const float4*)src)[lane];
    float4 v1 = ((const float4*)src)[lane+32];
    char4 q0, q1;
    #define QZ(x) (signed char)max(-127, min(127, __float2int_rn((x)*QSCALE)))
    q0.x=QZ(v0.x); q0.y=QZ(v0.y); q0.z=QZ(v0.z); q0.w=QZ(v0.w);
    q1.x=QZ(v1.x); q1.y=QZ(v1.y); q1.z=QZ(v1.z); q1.w=QZ(v1.w);
    #undef QZ
    ((char4*)dst)[lane]    = q0;
    ((char4*)dst)[lane+32] = q1;

    if(isface){
        float s = v0.x+v0.y+v0.z+v0.w + v1.x+v1.y+v1.z+v1.w;
        #pragma unroll
        for(int o=16;o;o>>=1) s += __shfl_xor_sync(0xffffffffu, s, o);
        if(lane==0) g_flag[row] = (s != 0.f) ? 1 : 0;
    }
}

// scan (R10 exact): single block; flags -> g_idx/g_rb (+pads), g_ntm
__global__ void __launch_bounds__(1024,1) frag_scan(){
    __shared__ int ws[32];
    __shared__ int tot;
    int t = threadIdx.x, lane = t&31, w = t>>5;
    int f[8], s = 0;
    #pragma unroll
    for(int i=0;i<8;i++){ f[i] = g_flag[t*8+i]; s += f[i]; }
    int pre = s;
    #pragma unroll
    for(int o=1;o<32;o<<=1){ int v = __shfl_up_sync(0xffffffffu, pre, o); if(lane>=o) pre += v; }
    if(lane==31) ws[w] = pre;
    __syncthreads();
    if(w==0){
        int v = ws[lane];
        #pragma unroll
        for(int o=1;o<32;o<<=1){ int x = __shfl_up_sync(0xffffffffu, v, o); if(lane>=o) v += x; }
        ws[lane] = v;
    }
    __syncthreads();
    int base = (w>0 ? ws[w-1] : 0) + pre - s;
    int p = base;
    #pragma unroll
    for(int i=0;i<8;i++){
        int row = t*8+i;
        if(f[i]){ g_idx[p] = row; g_rb[p] = row >> 5; p++; }
    }
    if(t==1023){ tot = p; g_ntm = (p + TM - 1)/TM; }
    __syncthreads();
    int count = tot, pad_end = ((count + TM - 1)/TM)*TM;
    for(int r = count + t; r < pad_end; r += 1024){
        g_idx[r] = RM + (r - count);
        g_rb[r]  = -1;
    }
}

extern "C" void kernel_launch(void* const* d_in, const int* in_sizes, int n_in,
                              void* d_out, int out_size){
    const float* face = (const float*)d_in[0];
    const float* ner  = (const float*)d_in[1];
    float* out = (float*)d_out;

    cudaFuncSetAttribute(frag_main, cudaFuncAttributeMaxDynamicSharedMemorySize, SMEM_TOTAL);

    frag_prep<<<(RM+RN)/8, 256>>>(face, ner);
    frag_scan<<<1, 1024>>>();
    frag_main<<<MAIN_GRID, NTHREADS, SMEM_TOTAL>>>(out);
}